// round 1
// baseline (speedup 1.0000x reference)
#include <cuda_runtime.h>
#include <math.h>

// ---------------- problem constants ----------------
#define HNUM 16
#define CDIM 4096
#define HD 64
#define BB 4
#define SS 256
#define DIN 1024
#define ATT 1024
#define RR 256
#define CRN 1024
#define SCN 2048
#define FFN 3072
#define EPSV 1e-5f

// ---------------- device scratch (no allocations allowed) ----------------
__device__ __align__(16) float g_q[HNUM*CDIM*HD];        //  16.8 MB
__device__ __align__(16) float g_qdet[HNUM*CDIM*HD];     //  16.8 MB
__device__ __align__(16) float g_qr[HNUM*RR*HD];         //   1.0 MB
__device__ __align__(16) float g_kvraw[BB*SS*2*ATT];     //   8.4 MB
__device__ __align__(16) float g_k[BB*HNUM*SS*HD];       //   4.2 MB
__device__ __align__(16) float g_v[BB*HNUM*SS*HD];       //   4.2 MB
__device__ __align__(16) float g_o[BB*CDIM*ATT];         //  67.1 MB
__device__ __align__(16) float g_ln[BB*CDIM*ATT];        //  67.1 MB
__device__ __align__(16) float g_f[BB*CDIM*2*FFN];       // 402.7 MB
__device__ __align__(16) float g_gate[BB*CDIM*FFN];      // 201.3 MB
__device__ __align__(16) float g_h[BB*CDIM*ATT];         //  67.1 MB

__device__ __forceinline__ float warp_sum(float v){
    #pragma unroll
    for (int o = 16; o; o >>= 1) v += __shfl_xor_sync(0xffffffffu, v, o);
    return v;
}
__device__ __forceinline__ float warp_max(float v){
    #pragma unroll
    for (int o = 16; o; o >>= 1) v = fmaxf(v, __shfl_xor_sync(0xffffffffu, v, o));
    return v;
}

// ---------------- generic float4 copy ----------------
__global__ void copy4_kernel(const float4* __restrict__ src, float4* __restrict__ dst, int n4){
    int i = blockIdx.x * blockDim.x + threadIdx.x;
    if (i < n4) dst[i] = src[i];
}

// ---------------- rmsnorm over rows of 64 (one warp per row) ----------------
__global__ void rms64_kernel(const float* __restrict__ in, float* __restrict__ out){
    int row = blockIdx.x, t = threadIdx.x;
    float2 v = ((const float2*)(in + (size_t)row*64))[t];
    float ss = v.x*v.x + v.y*v.y;
    ss = warp_sum(ss);
    float sc = rsqrtf(ss*(1.f/64.f) + EPSV);
    ((float2*)(out + (size_t)row*64))[t] = make_float2(v.x*sc, v.y*sc);
}

// ---------------- scatter-add: dst[h, dstidx[j], :] += src[h, srcidx[j], :] * w[h,j] ----------------
__global__ void scatter_kernel(const int* __restrict__ srcidx, const int* __restrict__ dstidx,
                               const float* __restrict__ w, const float* __restrict__ src,
                               float* __restrict__ dst, int nper, int src_rows){
    int j = blockIdx.x % nper;
    int h = blockIdx.x / nper;
    int r = srcidx[j];
    int c = dstidx[j];
    float ww = w[(size_t)h*nper + j];
    int t = threadIdx.x;  // 64
    atomicAdd(&dst[((size_t)h*CDIM + c)*64 + t], src[((size_t)h*src_rows + r)*64 + t] * ww);
}

// ---------------- split kv, rmsnorm k, layout (b,h,s,hd) ----------------
__global__ void kvsplit_kernel(const float* __restrict__ kvraw, float* __restrict__ kout,
                               float* __restrict__ vout){
    int bid = blockIdx.x;               // = (b*16+h)*256+s
    int t = threadIdx.x;                // 32
    int b = bid >> 12, h = (bid >> 8) & 15, s = bid & 255;
    size_t rowoff = ((size_t)(b*SS + s))*2048 + h*64;
    float2 kv = ((const float2*)(kvraw + rowoff))[t];
    float2 vv = ((const float2*)(kvraw + rowoff + 1024))[t];
    float ss = kv.x*kv.x + kv.y*kv.y;
    ss = warp_sum(ss);
    float sc = rsqrtf(ss*(1.f/64.f) + EPSV);
    ((float2*)(kout + (size_t)bid*64))[t] = make_float2(kv.x*sc, kv.y*sc);
    ((float2*)(vout + (size_t)bid*64))[t] = vv;
}

// ---------------- classic SGEMM: C[M,N] = A[M,K] @ B[N,K]^T, all row-major ----------------
__global__ void __launch_bounds__(256) sgemm_nt(const float* __restrict__ A,
                                                const float* __restrict__ B,
                                                float* __restrict__ C, int M, int N, int K){
    __shared__ float As[16][128];
    __shared__ float Bs[16][128];
    int tid = threadIdx.x;
    int bm = blockIdx.y << 7, bn = blockIdx.x << 7;
    int tx = tid & 15, ty = tid >> 4;
    float acc[8][8] = {};
    const float* Ab = A + (size_t)bm*K;
    const float* Bb = B + (size_t)bn*K;
    for (int k0 = 0; k0 < K; k0 += 16){
        #pragma unroll
        for (int i = 0; i < 2; i++){
            int idx = tid + (i << 8);
            int r = idx >> 2, c4 = (idx & 3) << 2;
            float4 av = *(const float4*)(Ab + (size_t)r*K + k0 + c4);
            As[c4  ][r] = av.x; As[c4+1][r] = av.y; As[c4+2][r] = av.z; As[c4+3][r] = av.w;
            float4 bv = *(const float4*)(Bb + (size_t)r*K + k0 + c4);
            Bs[c4  ][r] = bv.x; Bs[c4+1][r] = bv.y; Bs[c4+2][r] = bv.z; Bs[c4+3][r] = bv.w;
        }
        __syncthreads();
        #pragma unroll
        for (int kk = 0; kk < 16; kk++){
            float a[8], b[8];
            #pragma unroll
            for (int i = 0; i < 8; i++) a[i] = As[kk][(ty<<3)+i];
            #pragma unroll
            for (int j = 0; j < 8; j++) b[j] = Bs[kk][(tx<<3)+j];
            #pragma unroll
            for (int i = 0; i < 8; i++)
                #pragma unroll
                for (int j = 0; j < 8; j++) acc[i][j] = fmaf(a[i], b[j], acc[i][j]);
        }
        __syncthreads();
    }
    #pragma unroll
    for (int i = 0; i < 8; i++){
        size_t row = (size_t)bm + (ty<<3) + i;
        float* Cr = C + row*N + bn + (tx<<3);
        #pragma unroll
        for (int j = 0; j < 8; j += 4){
            *(float4*)(Cr + j) = make_float4(acc[i][j], acc[i][j+1], acc[i][j+2], acc[i][j+3]);
        }
    }
}

// ---------------- attention: one block per (b*h, c-tile of 256); k,v cached in smem ----------------
#define SROW 68
__global__ void __launch_bounds__(256) attn_kernel(const float* __restrict__ q,
                                                   const float* __restrict__ k,
                                                   const float* __restrict__ v,
                                                   float* __restrict__ o){
    extern __shared__ float sm[];
    float* ks = sm;                     // 256*68
    float* vs = ks + 256*SROW;          // 256*68
    float* qs = vs + 256*SROW;          // 64
    float* at = qs + 64;                // 256
    float* op = at + 256;               // 256
    float* rd = op + 256;               // 16
    int tid = threadIdx.x;
    int bh = blockIdx.x;
    int b = bh >> 4, h = bh & 15;
    size_t base = (size_t)bh * SS * HD;
    for (int i = tid; i < SS*16; i += 256){
        int s = i >> 4, c4 = (i & 15) << 2;
        float4 kk = *(const float4*)(k + base + (size_t)s*64 + c4);
        float4 vv = *(const float4*)(v + base + (size_t)s*64 + c4);
        ks[s*SROW+c4] = kk.x; ks[s*SROW+c4+1] = kk.y; ks[s*SROW+c4+2] = kk.z; ks[s*SROW+c4+3] = kk.w;
        vs[s*SROW+c4] = vv.x; vs[s*SROW+c4+1] = vv.y; vs[s*SROW+c4+2] = vv.z; vs[s*SROW+c4+3] = vv.w;
    }
    __syncthreads();
    int c0 = blockIdx.y << 8;
    for (int c = 0; c < 256; c++){
        int cc = c0 + c;
        if (tid < 16){
            float4 qv = *(const float4*)(q + ((size_t)h*CDIM + cc)*64 + (tid << 2));
            qs[tid*4] = qv.x; qs[tid*4+1] = qv.y; qs[tid*4+2] = qv.z; qs[tid*4+3] = qv.w;
        }
        __syncthreads();
        float sc = 0.f;
        #pragma unroll
        for (int e = 0; e < 64; e += 4){
            float4 kk = *(float4*)&ks[tid*SROW + e];
            sc += kk.x*qs[e] + kk.y*qs[e+1] + kk.z*qs[e+2] + kk.w*qs[e+3];
        }
        sc *= 0.125f;  // 1/sqrt(64)
        float wmax = warp_max(sc);
        if ((tid & 31) == 0) rd[tid >> 5] = wmax;
        __syncthreads();
        float bmax = rd[0];
        #pragma unroll
        for (int i = 1; i < 8; i++) bmax = fmaxf(bmax, rd[i]);
        float ex = __expf(sc - bmax);
        at[tid] = ex;
        float wsum = warp_sum(ex);
        if ((tid & 31) == 0) rd[8 + (tid >> 5)] = wsum;
        __syncthreads();
        float bsum = 0.f;
        #pragma unroll
        for (int i = 0; i < 8; i++) bsum += rd[8 + i];
        float inv = 1.f / bsum;
        int e = tid & 63, ch = tid >> 6;
        float acc = 0.f;
        #pragma unroll 8
        for (int i = 0; i < 64; i++){
            int s = (ch << 6) + i;
            acc = fmaf(at[s], vs[s*SROW + e], acc);
        }
        op[tid] = acc;
        __syncthreads();
        if (tid < 64){
            float oo = (op[tid] + op[64+tid] + op[128+tid] + op[192+tid]) * inv;
            o[((size_t)b*CDIM + cc)*ATT + h*64 + tid] = oo;
        }
        __syncthreads();
    }
}

// ---------------- layernorm rows of 1024 ----------------
__global__ void __launch_bounds__(256) ln_kernel(const float* __restrict__ gamma,
                                                 const float* __restrict__ beta,
                                                 const float* __restrict__ in,
                                                 float* __restrict__ out){
    __shared__ float rs[8], rq[8];
    int row = blockIdx.x, tid = threadIdx.x;
    float4 v = ((const float4*)(in + (size_t)row*ATT))[tid];
    float s = v.x+v.y+v.z+v.w;
    float q = v.x*v.x+v.y*v.y+v.z*v.z+v.w*v.w;
    s = warp_sum(s); q = warp_sum(q);
    if ((tid & 31) == 0){ rs[tid>>5] = s; rq[tid>>5] = q; }
    __syncthreads();
    float ts = 0.f, tq = 0.f;
    #pragma unroll
    for (int i = 0; i < 8; i++){ ts += rs[i]; tq += rq[i]; }
    float mu = ts * (1.f/1024.f);
    float var = tq * (1.f/1024.f) - mu*mu;
    float rr = rsqrtf(var + EPSV);
    float4 g4 = ((const float4*)gamma)[tid];
    float4 b4 = ((const float4*)beta)[tid];
    float4 o4;
    o4.x = (v.x-mu)*rr*g4.x + b4.x;
    o4.y = (v.y-mu)*rr*g4.y + b4.y;
    o4.z = (v.z-mu)*rr*g4.z + b4.z;
    o4.w = (v.w-mu)*rr*g4.w + b4.w;
    ((float4*)(out + (size_t)row*ATT))[tid] = o4;
}

// ---------------- gate: g = silu(f1) * f2 ----------------
__global__ void gate_kernel(const float* __restrict__ f, float* __restrict__ g, int n){
    int i = blockIdx.x * blockDim.x + threadIdx.x;
    if (i >= n) return;
    int m = i / FFN, j = i - m*FFN;
    float f1 = f[(size_t)m*2*FFN + j];
    float f2 = f[(size_t)m*2*FFN + FFN + j];
    g[i] = f1 / (1.f + __expf(-f1)) * f2;
}

// ---------------- final: z = o+h; y = z @ out_w[c]; out = silu(y0)*y1 ----------------
__global__ void __launch_bounds__(256) final_kernel(const float* __restrict__ ow,
                                                    const float* __restrict__ o,
                                                    const float* __restrict__ h,
                                                    float* __restrict__ out){
    __shared__ float r0[8], r1[8];
    int row = blockIdx.x, tid = threadIdx.x;
    int c = row & (CDIM-1);
    const float2* w = (const float2*)(ow + (size_t)c*2048);
    float a0 = 0.f, a1 = 0.f;
    #pragma unroll
    for (int it = 0; it < 4; it++){
        int a = tid + it*256;
        float z = o[(size_t)row*ATT + a] + h[(size_t)row*ATT + a];
        float2 ww = w[a];
        a0 = fmaf(z, ww.x, a0);
        a1 = fmaf(z, ww.y, a1);
    }
    a0 = warp_sum(a0); a1 = warp_sum(a1);
    if ((tid & 31) == 0){ r0[tid>>5] = a0; r1[tid>>5] = a1; }
    __syncthreads();
    if (tid == 0){
        float y0 = 0.f, y1 = 0.f;
        #pragma unroll
        for (int i = 0; i < 8; i++){ y0 += r0[i]; y1 += r1[i]; }
        out[row] = y0 / (1.f + __expf(-y0)) * y1;
    }
}

// ---------------- launch ----------------
extern "C" void kernel_launch(void* const* d_in, const int* in_sizes, int n_in,
                              void* d_out, int out_size){
    const float* x        = (const float*)d_in[0];
    const float* cls      = (const float*)d_in[1];
    const float* roots    = (const float*)d_in[2];
    const float* cr_w     = (const float*)d_in[3];
    const float* cc_w     = (const float*)d_in[4];
    const float* kv_w     = (const float*)d_in[5];
    const float* ln_gamma = (const float*)d_in[6];
    const float* ln_beta  = (const float*)d_in[7];
    const float* ff_in_w  = (const float*)d_in[8];
    const float* ff_out_w = (const float*)d_in[9];
    const float* out_w    = (const float*)d_in[10];
    const int*   cr_idx   = (const int*)d_in[11];
    const int*   cc_idx   = (const int*)d_in[12];
    float* out = (float*)d_out;

    void *pq, *pqdet, *pqr, *pkvraw, *pk, *pv, *po, *pln, *pf, *pg, *ph;
    cudaGetSymbolAddress(&pq, g_q);
    cudaGetSymbolAddress(&pqdet, g_qdet);
    cudaGetSymbolAddress(&pqr, g_qr);
    cudaGetSymbolAddress(&pkvraw, g_kvraw);
    cudaGetSymbolAddress(&pk, g_k);
    cudaGetSymbolAddress(&pv, g_v);
    cudaGetSymbolAddress(&po, g_o);
    cudaGetSymbolAddress(&pln, g_ln);
    cudaGetSymbolAddress(&pf, g_f);
    cudaGetSymbolAddress(&pg, g_gate);
    cudaGetSymbolAddress(&ph, g_h);

    static int smem_set = 0;
    int attn_smem = (2*256*SROW + 64 + 256 + 256 + 16) * 4;
    if (!smem_set){
        cudaFuncSetAttribute(attn_kernel, cudaFuncAttributeMaxDynamicSharedMemorySize, attn_smem);
        smem_set = 1;
    }

    // 1. q = copy(cls)
    copy4_kernel<<<(HNUM*CDIM*HD/4 + 255)/256, 256>>>((const float4*)cls, (float4*)pq, HNUM*CDIM*HD/4);
    // 2. qr = rmsnorm(roots)
    rms64_kernel<<<HNUM*RR, 32>>>(roots, (float*)pqr);
    // 3. scatter 1: q[h, cr_idx1, :] += qr[h, cr_idx0, :] * cr_w
    scatter_kernel<<<HNUM*CRN, 64>>>(cr_idx, cr_idx + CRN, cr_w, (const float*)pqr, (float*)pq, CRN, RR);
    // 4. snapshot q_det
    copy4_kernel<<<(HNUM*CDIM*HD/4 + 255)/256, 256>>>((const float4*)pq, (float4*)pqdet, HNUM*CDIM*HD/4);
    // 5. scatter 2: q[h, cc_idx1, :] += q_det[h, cc_idx0, :] * cc_w
    scatter_kernel<<<HNUM*SCN, 64>>>(cc_idx, cc_idx + SCN, cc_w, (const float*)pqdet, (float*)pq, SCN, CDIM);
    // 6. q = rmsnorm(q)
    rms64_kernel<<<HNUM*CDIM, 32>>>((const float*)pq, (float*)pq);
    // 7. kv = x @ kv_w^T : (1024, 2048)
    sgemm_nt<<<dim3(2048/128, 1024/128), 256>>>(x, kv_w, (float*)pkvraw, BB*SS, 2*ATT, DIN);
    // 8. split k/v, rmsnorm k
    kvsplit_kernel<<<BB*HNUM*SS, 32>>>((const float*)pkvraw, (float*)pk, (float*)pv);
    // 9. attention
    attn_kernel<<<dim3(BB*HNUM, CDIM/256), 256, attn_smem>>>((const float*)pq, (const float*)pk,
                                                             (const float*)pv, (float*)po);
    // 10. layernorm(o)
    ln_kernel<<<BB*CDIM, 256>>>(ln_gamma, ln_beta, (const float*)po, (float*)pln);
    // 11. f = ln @ ff_in_w^T : (16384, 6144)
    sgemm_nt<<<dim3(2*FFN/128, BB*CDIM/128), 256>>>((const float*)pln, ff_in_w, (float*)pf,
                                                    BB*CDIM, 2*FFN, ATT);
    // 12. gate
    {
        int n = BB*CDIM*FFN;
        gate_kernel<<<(n + 255)/256, 256>>>((const float*)pf, (float*)pg, n);
    }
    // 13. h = gate @ ff_out_w^T : (16384, 1024)
    sgemm_nt<<<dim3(ATT/128, BB*CDIM/128), 256>>>((const float*)pg, ff_out_w, (float*)ph,
                                                  BB*CDIM, ATT, FFN);
    // 14. final
    final_kernel<<<BB*CDIM, 256>>>(out_w, (const float*)po, (const float*)ph, out);
}

// round 3
// speedup vs baseline: 1.7422x; 1.7422x over previous
#include <cuda_runtime.h>
#include <cuda_bf16.h>
#include <cstdint>
#include <math.h>

// ---------------- problem constants ----------------
#define HNUM 16
#define CDIM 4096
#define HD 64
#define BB 4
#define SS 256
#define DIN 1024
#define ATT 1024
#define RR 256
#define CRN 1024
#define SCN 2048
#define FFN 3072
#define EPSV 1e-5f

// ---------------- device scratch (no allocations allowed) ----------------
__device__ __align__(16) float g_q[HNUM*CDIM*HD];
__device__ __align__(16) float g_qdet[HNUM*CDIM*HD];
__device__ __align__(16) float g_qr[HNUM*RR*HD];
__device__ __align__(16) float g_kvraw[BB*SS*2*ATT];
__device__ __align__(16) float g_k[BB*HNUM*SS*HD];
__device__ __align__(16) float g_v[BB*HNUM*SS*HD];
__device__ __align__(16) float g_o[BB*CDIM*ATT];
__device__ __align__(16) float g_f[(size_t)BB*CDIM*2*FFN];
__device__ __align__(16) float g_h[BB*CDIM*ATT];

// bf16 split buffers
__device__ __align__(16) __nv_bfloat16 g_xhi[BB*SS*DIN],        g_xlo[BB*SS*DIN];
__device__ __align__(16) __nv_bfloat16 g_kvwhi[2*ATT*DIN],      g_kvwlo[2*ATT*DIN];
__device__ __align__(16) __nv_bfloat16 g_lnhi[BB*CDIM*ATT],     g_lnlo[BB*CDIM*ATT];
__device__ __align__(16) __nv_bfloat16 g_ffinhi[2*FFN*ATT],     g_ffinlo[2*FFN*ATT];
__device__ __align__(16) __nv_bfloat16 g_ghi[(size_t)BB*CDIM*FFN], g_glo[(size_t)BB*CDIM*FFN];
__device__ __align__(16) __nv_bfloat16 g_ffouthi[ATT*FFN],      g_ffoutlo[ATT*FFN];

__device__ __forceinline__ float warp_sum(float v){
    #pragma unroll
    for (int o = 16; o; o >>= 1) v += __shfl_xor_sync(0xffffffffu, v, o);
    return v;
}
__device__ __forceinline__ float warp_max(float v){
    #pragma unroll
    for (int o = 16; o; o >>= 1) v = fmaxf(v, __shfl_xor_sync(0xffffffffu, v, o));
    return v;
}

// ---------------- generic float4 copy ----------------
__global__ void copy4_kernel(const float4* __restrict__ src, float4* __restrict__ dst, int n4){
    int i = blockIdx.x * blockDim.x + threadIdx.x;
    if (i < n4) dst[i] = src[i];
}

// ---------------- fp32 -> (hi, lo) bf16 split ----------------
__global__ void split_kernel(const float4* __restrict__ in, __nv_bfloat16* __restrict__ hi,
                             __nv_bfloat16* __restrict__ lo, int n4){
    int i = blockIdx.x * blockDim.x + threadIdx.x;
    if (i >= n4) return;
    float4 v = in[i];
    float vv[4] = {v.x, v.y, v.z, v.w};
    __nv_bfloat16 h[4], l[4];
    #pragma unroll
    for (int j = 0; j < 4; j++){
        h[j] = __float2bfloat16(vv[j]);
        l[j] = __float2bfloat16(vv[j] - __bfloat162float(h[j]));
    }
    *(uint2*)&hi[(size_t)i*4] = *(uint2*)h;
    *(uint2*)&lo[(size_t)i*4] = *(uint2*)l;
}

// ---------------- rmsnorm over rows of 64 (one warp per row) ----------------
__global__ void rms64_kernel(const float* __restrict__ in, float* __restrict__ out){
    int row = blockIdx.x, t = threadIdx.x;
    float2 v = ((const float2*)(in + (size_t)row*64))[t];
    float ss = v.x*v.x + v.y*v.y;
    ss = warp_sum(ss);
    float sc = rsqrtf(ss*(1.f/64.f) + EPSV);
    ((float2*)(out + (size_t)row*64))[t] = make_float2(v.x*sc, v.y*sc);
}

// ---------------- scatter-add ----------------
__global__ void scatter_kernel(const int* __restrict__ srcidx, const int* __restrict__ dstidx,
                               const float* __restrict__ w, const float* __restrict__ src,
                               float* __restrict__ dst, int nper, int src_rows){
    int j = blockIdx.x % nper;
    int h = blockIdx.x / nper;
    int r = srcidx[j];
    int c = dstidx[j];
    float ww = w[(size_t)h*nper + j];
    int t = threadIdx.x;  // 64
    atomicAdd(&dst[((size_t)h*CDIM + c)*64 + t], src[((size_t)h*src_rows + r)*64 + t] * ww);
}

// ---------------- split kv, rmsnorm k ----------------
__global__ void kvsplit_kernel(const float* __restrict__ kvraw, float* __restrict__ kout,
                               float* __restrict__ vout){
    int bid = blockIdx.x;               // (b*16+h)*256+s
    int t = threadIdx.x;                // 32
    int b = bid >> 12, h = (bid >> 8) & 15, s = bid & 255;
    size_t rowoff = ((size_t)(b*SS + s))*2048 + h*64;
    float2 kv = ((const float2*)(kvraw + rowoff))[t];
    float2 vv = ((const float2*)(kvraw + rowoff + 1024))[t];
    float ss = kv.x*kv.x + kv.y*kv.y;
    ss = warp_sum(ss);
    float sc = rsqrtf(ss*(1.f/64.f) + EPSV);
    ((float2*)(kout + (size_t)bid*64))[t] = make_float2(kv.x*sc, kv.y*sc);
    ((float2*)(vout + (size_t)bid*64))[t] = vv;
}

// ---------------- split-bf16 tensor-core GEMM: C[M,N] = A[M,K] @ B[N,K]^T ----------------
// A,B given as (hi,lo) bf16 pairs; D = Ahi*Bhi + Ahi*Blo + Alo*Bhi  (fp32 accum)
#define PKW 20   // padded SMEM row stride in 32-bit words (= 40 bf16 for 32 data cols)

__device__ __forceinline__ void mma16816(float* d, const unsigned int* a, const unsigned int* b){
    asm volatile(
        "mma.sync.aligned.m16n8k16.row.col.f32.bf16.bf16.f32 "
        "{%0,%1,%2,%3}, {%4,%5,%6,%7}, {%8,%9}, {%0,%1,%2,%3};\n"
        : "+f"(d[0]), "+f"(d[1]), "+f"(d[2]), "+f"(d[3])
        : "r"(a[0]), "r"(a[1]), "r"(a[2]), "r"(a[3]), "r"(b[0]), "r"(b[1]));
}

__global__ void __launch_bounds__(256) gemm_nt_split(
    const __nv_bfloat16* __restrict__ Ahi, const __nv_bfloat16* __restrict__ Alo,
    const __nv_bfloat16* __restrict__ Bhi, const __nv_bfloat16* __restrict__ Blo,
    float* __restrict__ C, int M, int N, int K)
{
    __shared__ unsigned int sAh[128*PKW], sAl[128*PKW], sBh[128*PKW], sBl[128*PKW];
    int tid = threadIdx.x;
    int bm = blockIdx.y << 7, bn = blockIdx.x << 7;
    int warp = tid >> 5, lane = tid & 31;
    int g = lane >> 2, tg = lane & 3;
    int wm = (warp >> 1) << 5;   // 0,32,64,96
    int wn = (warp & 1) << 6;    // 0,64
    float acc[2][8][4] = {};

    const __nv_bfloat16* Ah = Ahi + (size_t)bm*K;
    const __nv_bfloat16* Al = Alo + (size_t)bm*K;
    const __nv_bfloat16* Bh = Bhi + (size_t)bn*K;
    const __nv_bfloat16* Bl = Blo + (size_t)bn*K;

    int ldr = tid >> 2;                  // 0..63 (+64 on second it)
    int ldc = (tid & 3) << 3;            // 0,8,16,24 (bf16 col)

    for (int k0 = 0; k0 < K; k0 += 32){
        #pragma unroll
        for (int it = 0; it < 2; it++){
            int r = ldr + (it << 6);
            size_t go = (size_t)r*K + k0 + ldc;
            int so = r*40 + ldc;         // bf16 units, row stride 40
            *(float4*)((__nv_bfloat16*)sAh + so) = *(const float4*)(Ah + go);
            *(float4*)((__nv_bfloat16*)sAl + so) = *(const float4*)(Al + go);
            *(float4*)((__nv_bfloat16*)sBh + so) = *(const float4*)(Bh + go);
            *(float4*)((__nv_bfloat16*)sBl + so) = *(const float4*)(Bl + go);
        }
        __syncthreads();
        #pragma unroll
        for (int ks = 0; ks < 2; ks++){
            int kw = (ks << 3) + tg;
            unsigned int ah[2][4], al[2][4];
            #pragma unroll
            for (int mt = 0; mt < 2; mt++){
                int r0 = wm + (mt << 4) + g;
                ah[mt][0] = sAh[r0*PKW + kw];
                ah[mt][1] = sAh[(r0+8)*PKW + kw];
                ah[mt][2] = sAh[r0*PKW + kw + 4];
                ah[mt][3] = sAh[(r0+8)*PKW + kw + 4];
                al[mt][0] = sAl[r0*PKW + kw];
                al[mt][1] = sAl[(r0+8)*PKW + kw];
                al[mt][2] = sAl[r0*PKW + kw + 4];
                al[mt][3] = sAl[(r0+8)*PKW + kw + 4];
            }
            unsigned int bh[8][2], bl[8][2];
            #pragma unroll
            for (int nt = 0; nt < 8; nt++){
                int n0 = wn + (nt << 3) + g;
                bh[nt][0] = sBh[n0*PKW + kw];
                bh[nt][1] = sBh[n0*PKW + kw + 4];
                bl[nt][0] = sBl[n0*PKW + kw];
                bl[nt][1] = sBl[n0*PKW + kw + 4];
            }
            #pragma unroll
            for (int mt = 0; mt < 2; mt++)
                #pragma unroll
                for (int nt = 0; nt < 8; nt++){
                    mma16816(acc[mt][nt], ah[mt], bh[nt]);
                    mma16816(acc[mt][nt], ah[mt], bl[nt]);
                    mma16816(acc[mt][nt], al[mt], bh[nt]);
                }
        }
        __syncthreads();
    }
    #pragma unroll
    for (int mt = 0; mt < 2; mt++){
        #pragma unroll
        for (int nt = 0; nt < 8; nt++){
            size_t row0 = (size_t)bm + wm + (mt << 4) + g;
            int col = bn + wn + (nt << 3) + (tg << 1);
            *(float2*)&C[row0*N + col]      = make_float2(acc[mt][nt][0], acc[mt][nt][1]);
            *(float2*)&C[(row0+8)*N + col]  = make_float2(acc[mt][nt][2], acc[mt][nt][3]);
        }
    }
}

// ---------------- attention: one block per (b*h, c-tile of 256) ----------------
#define SROW 68
__global__ void __launch_bounds__(256) attn_kernel(const float* __restrict__ q,
                                                   const float* __restrict__ k,
                                                   const float* __restrict__ v,
                                                   float* __restrict__ o){
    extern __shared__ float sm[];
    float* ks = sm;
    float* vs = ks + 256*SROW;
    float* qs = vs + 256*SROW;
    float* at = qs + 64;
    float* op = at + 256;
    float* rd = op + 256;
    int tid = threadIdx.x;
    int bh = blockIdx.x;
    int b = bh >> 4, h = bh & 15;
    size_t base = (size_t)bh * SS * HD;
    for (int i = tid; i < SS*16; i += 256){
        int s = i >> 4, c4 = (i & 15) << 2;
        float4 kk = *(const float4*)(k + base + (size_t)s*64 + c4);
        float4 vv = *(const float4*)(v + base + (size_t)s*64 + c4);
        ks[s*SROW+c4] = kk.x; ks[s*SROW+c4+1] = kk.y; ks[s*SROW+c4+2] = kk.z; ks[s*SROW+c4+3] = kk.w;
        vs[s*SROW+c4] = vv.x; vs[s*SROW+c4+1] = vv.y; vs[s*SROW+c4+2] = vv.z; vs[s*SROW+c4+3] = vv.w;
    }
    __syncthreads();
    int c0 = blockIdx.y << 8;
    for (int c = 0; c < 256; c++){
        int cc = c0 + c;
        if (tid < 16){
            float4 qv = *(const float4*)(q + ((size_t)h*CDIM + cc)*64 + (tid << 2));
            qs[tid*4] = qv.x; qs[tid*4+1] = qv.y; qs[tid*4+2] = qv.z; qs[tid*4+3] = qv.w;
        }
        __syncthreads();
        float sc = 0.f;
        #pragma unroll
        for (int e = 0; e < 64; e += 4){
            float4 kk = *(float4*)&ks[tid*SROW + e];
            sc += kk.x*qs[e] + kk.y*qs[e+1] + kk.z*qs[e+2] + kk.w*qs[e+3];
        }
        sc *= 0.125f;
        float wmax = warp_max(sc);
        if ((tid & 31) == 0) rd[tid >> 5] = wmax;
        __syncthreads();
        float bmax = rd[0];
        #pragma unroll
        for (int i = 1; i < 8; i++) bmax = fmaxf(bmax, rd[i]);
        float ex = __expf(sc - bmax);
        at[tid] = ex;
        float wsum = warp_sum(ex);
        if ((tid & 31) == 0) rd[8 + (tid >> 5)] = wsum;
        __syncthreads();
        float bsum = 0.f;
        #pragma unroll
        for (int i = 0; i < 8; i++) bsum += rd[8 + i];
        float inv = 1.f / bsum;
        int e = tid & 63, ch = tid >> 6;
        float acc = 0.f;
        #pragma unroll 8
        for (int i = 0; i < 64; i++){
            int s = (ch << 6) + i;
            acc = fmaf(at[s], vs[s*SROW + e], acc);
        }
        op[tid] = acc;
        __syncthreads();
        if (tid < 64){
            float oo = (op[tid] + op[64+tid] + op[128+tid] + op[192+tid]) * inv;
            o[((size_t)b*CDIM + cc)*ATT + h*64 + tid] = oo;
        }
        __syncthreads();
    }
}

// ---------------- layernorm rows of 1024, fused bf16 split output ----------------
__global__ void __launch_bounds__(256) ln_split_kernel(const float* __restrict__ gamma,
                                                       const float* __restrict__ beta,
                                                       const float* __restrict__ in,
                                                       __nv_bfloat16* __restrict__ hi,
                                                       __nv_bfloat16* __restrict__ lo){
    __shared__ float rs[8], rq[8];
    int row = blockIdx.x, tid = threadIdx.x;
    float4 v = ((const float4*)(in + (size_t)row*ATT))[tid];
    float s = v.x+v.y+v.z+v.w;
    float q = v.x*v.x+v.y*v.y+v.z*v.z+v.w*v.w;
    s = warp_sum(s); q = warp_sum(q);
    if ((tid & 31) == 0){ rs[tid>>5] = s; rq[tid>>5] = q; }
    __syncthreads();
    float ts = 0.f, tq = 0.f;
    #pragma unroll
    for (int i = 0; i < 8; i++){ ts += rs[i]; tq += rq[i]; }
    float mu = ts * (1.f/1024.f);
    float var = tq * (1.f/1024.f) - mu*mu;
    float rr = rsqrtf(var + EPSV);
    float4 g4 = ((const float4*)gamma)[tid];
    float4 b4 = ((const float4*)beta)[tid];
    float ov[4];
    ov[0] = (v.x-mu)*rr*g4.x + b4.x;
    ov[1] = (v.y-mu)*rr*g4.y + b4.y;
    ov[2] = (v.z-mu)*rr*g4.z + b4.z;
    ov[3] = (v.w-mu)*rr*g4.w + b4.w;
    __nv_bfloat16 h[4], l[4];
    #pragma unroll
    for (int j = 0; j < 4; j++){
        h[j] = __float2bfloat16(ov[j]);
        l[j] = __float2bfloat16(ov[j] - __bfloat162float(h[j]));
    }
    size_t off = (size_t)row*ATT + tid*4;
    *(uint2*)&hi[off] = *(uint2*)h;
    *(uint2*)&lo[off] = *(uint2*)l;
}

// ---------------- gate: g = silu(f1)*f2, fused bf16 split output ----------------
__global__ void gate_split_kernel(const float* __restrict__ f,
                                  __nv_bfloat16* __restrict__ ghi,
                                  __nv_bfloat16* __restrict__ glo, int n4){
    int i = blockIdx.x * blockDim.x + threadIdx.x;
    if (i >= n4) return;
    size_t e = (size_t)i*4;
    size_t m = e / FFN;
    int j = (int)(e - m*FFN);
    float4 f1 = *(const float4*)&f[m*2*FFN + j];
    float4 f2 = *(const float4*)&f[m*2*FFN + FFN + j];
    float gg[4];
    gg[0] = f1.x / (1.f + __expf(-f1.x)) * f2.x;
    gg[1] = f1.y / (1.f + __expf(-f1.y)) * f2.y;
    gg[2] = f1.z / (1.f + __expf(-f1.z)) * f2.z;
    gg[3] = f1.w / (1.f + __expf(-f1.w)) * f2.w;
    __nv_bfloat16 h[4], l[4];
    #pragma unroll
    for (int q = 0; q < 4; q++){
        h[q] = __float2bfloat16(gg[q]);
        l[q] = __float2bfloat16(gg[q] - __bfloat162float(h[q]));
    }
    *(uint2*)&ghi[e] = *(uint2*)h;
    *(uint2*)&glo[e] = *(uint2*)l;
}

// ---------------- final: z = o+h; y = z @ out_w[c]; out = silu(y0)*y1 ----------------
__global__ void __launch_bounds__(256) final_kernel(const float* __restrict__ ow,
                                                    const float* __restrict__ o,
                                                    const float* __restrict__ h,
                                                    float* __restrict__ out){
    __shared__ float r0[8], r1[8];
    int row = blockIdx.x, tid = threadIdx.x;
    int c = row & (CDIM-1);
    const float2* w = (const float2*)(ow + (size_t)c*2048);
    float a0 = 0.f, a1 = 0.f;
    #pragma unroll
    for (int it = 0; it < 4; it++){
        int a = tid + it*256;
        float z = o[(size_t)row*ATT + a] + h[(size_t)row*ATT + a];
        float2 ww = w[a];
        a0 = fmaf(z, ww.x, a0);
        a1 = fmaf(z, ww.y, a1);
    }
    a0 = warp_sum(a0); a1 = warp_sum(a1);
    if ((tid & 31) == 0){ r0[tid>>5] = a0; r1[tid>>5] = a1; }
    __syncthreads();
    if (tid == 0){
        float y0 = 0.f, y1 = 0.f;
        #pragma unroll
        for (int i = 0; i < 8; i++){ y0 += r0[i]; y1 += r1[i]; }
        out[row] = y0 / (1.f + __expf(-y0)) * y1;
    }
}

// ---------------- launch ----------------
extern "C" void kernel_launch(void* const* d_in, const int* in_sizes, int n_in,
                              void* d_out, int out_size){
    const float* x        = (const float*)d_in[0];
    const float* cls      = (const float*)d_in[1];
    const float* roots    = (const float*)d_in[2];
    const float* cr_w     = (const float*)d_in[3];
    const float* cc_w     = (const float*)d_in[4];
    const float* kv_w     = (const float*)d_in[5];
    const float* ln_gamma = (const float*)d_in[6];
    const float* ln_beta  = (const float*)d_in[7];
    const float* ff_in_w  = (const float*)d_in[8];
    const float* ff_out_w = (const float*)d_in[9];
    const float* out_w    = (const float*)d_in[10];
    const int*   cr_idx   = (const int*)d_in[11];
    const int*   cc_idx   = (const int*)d_in[12];
    float* out = (float*)d_out;

    void *pq, *pqdet, *pqr, *pkvraw, *pk, *pv, *po, *pf, *ph;
    void *pxhi, *pxlo, *pkvwhi, *pkvwlo, *plnhi, *plnlo, *pffinhi, *pffinlo;
    void *pghi, *pglo, *pffouthi, *pffoutlo;
    cudaGetSymbolAddress(&pq, g_q);
    cudaGetSymbolAddress(&pqdet, g_qdet);
    cudaGetSymbolAddress(&pqr, g_qr);
    cudaGetSymbolAddress(&pkvraw, g_kvraw);
    cudaGetSymbolAddress(&pk, g_k);
    cudaGetSymbolAddress(&pv, g_v);
    cudaGetSymbolAddress(&po, g_o);
    cudaGetSymbolAddress(&pf, g_f);
    cudaGetSymbolAddress(&ph, g_h);
    cudaGetSymbolAddress(&pxhi, g_xhi);       cudaGetSymbolAddress(&pxlo, g_xlo);
    cudaGetSymbolAddress(&pkvwhi, g_kvwhi);   cudaGetSymbolAddress(&pkvwlo, g_kvwlo);
    cudaGetSymbolAddress(&plnhi, g_lnhi);     cudaGetSymbolAddress(&plnlo, g_lnlo);
    cudaGetSymbolAddress(&pffinhi, g_ffinhi); cudaGetSymbolAddress(&pffinlo, g_ffinlo);
    cudaGetSymbolAddress(&pghi, g_ghi);       cudaGetSymbolAddress(&pglo, g_glo);
    cudaGetSymbolAddress(&pffouthi, g_ffouthi); cudaGetSymbolAddress(&pffoutlo, g_ffoutlo);

    int attn_smem = (2*256*SROW + 64 + 256 + 256 + 16) * 4;
    cudaFuncSetAttribute(attn_kernel, cudaFuncAttributeMaxDynamicSharedMemorySize, attn_smem);

    // ---- q preparation ----
    copy4_kernel<<<(HNUM*CDIM*HD/4 + 255)/256, 256>>>((const float4*)cls, (float4*)pq, HNUM*CDIM*HD/4);
    rms64_kernel<<<HNUM*RR, 32>>>(roots, (float*)pqr);
    scatter_kernel<<<HNUM*CRN, 64>>>(cr_idx, cr_idx + CRN, cr_w, (const float*)pqr, (float*)pq, CRN, RR);
    copy4_kernel<<<(HNUM*CDIM*HD/4 + 255)/256, 256>>>((const float4*)pq, (float4*)pqdet, HNUM*CDIM*HD/4);
    scatter_kernel<<<HNUM*SCN, 64>>>(cc_idx, cc_idx + SCN, cc_w, (const float*)pqdet, (float*)pq, SCN, CDIM);
    rms64_kernel<<<HNUM*CDIM, 32>>>((const float*)pq, (float*)pq);

    // ---- kv = x @ kv_w^T on tensor cores ----
    split_kernel<<<(BB*SS*DIN/4 + 255)/256, 256>>>((const float4*)x, (__nv_bfloat16*)pxhi,
                                                   (__nv_bfloat16*)pxlo, BB*SS*DIN/4);
    split_kernel<<<(2*ATT*DIN/4 + 255)/256, 256>>>((const float4*)kv_w, (__nv_bfloat16*)pkvwhi,
                                                   (__nv_bfloat16*)pkvwlo, 2*ATT*DIN/4);
    gemm_nt_split<<<dim3(2*ATT/128, BB*SS/128), 256>>>(
        (const __nv_bfloat16*)pxhi, (const __nv_bfloat16*)pxlo,
        (const __nv_bfloat16*)pkvwhi, (const __nv_bfloat16*)pkvwlo,
        (float*)pkvraw, BB*SS, 2*ATT, DIN);
    kvsplit_kernel<<<BB*HNUM*SS, 32>>>((const float*)pkvraw, (float*)pk, (float*)pv);

    // ---- attention ----
    attn_kernel<<<dim3(BB*HNUM, CDIM/256), 256, attn_smem>>>((const float*)pq, (const float*)pk,
                                                             (const float*)pv, (float*)po);

    // ---- layernorm + split ----
    ln_split_kernel<<<BB*CDIM, 256>>>(ln_gamma, ln_beta, (const float*)po,
                                      (__nv_bfloat16*)plnhi, (__nv_bfloat16*)plnlo);

    // ---- FF1: f = ln @ ff_in_w^T (16384 x 6144 x 1024) ----
    split_kernel<<<(2*FFN*ATT/4 + 255)/256, 256>>>((const float4*)ff_in_w, (__nv_bfloat16*)pffinhi,
                                                   (__nv_bfloat16*)pffinlo, 2*FFN*ATT/4);
    gemm_nt_split<<<dim3(2*FFN/128, BB*CDIM/128), 256>>>(
        (const __nv_bfloat16*)plnhi, (const __nv_bfloat16*)plnlo,
        (const __nv_bfloat16*)pffinhi, (const __nv_bfloat16*)pffinlo,
        (float*)pf, BB*CDIM, 2*FFN, ATT);

    // ---- gate + split ----
    {
        int n4 = BB*CDIM*FFN/4;
        gate_split_kernel<<<(n4 + 255)/256, 256>>>((const float*)pf, (__nv_bfloat16*)pghi,
                                                   (__nv_bfloat16*)pglo, n4);
    }

    // ---- FF2: h = gate @ ff_out_w^T (16384 x 1024 x 3072) ----
    split_kernel<<<(ATT*FFN/4 + 255)/256, 256>>>((const float4*)ff_out_w, (__nv_bfloat16*)pffouthi,
                                                 (__nv_bfloat16*)pffoutlo, ATT*FFN/4);
    gemm_nt_split<<<dim3(ATT/128, BB*CDIM/128), 256>>>(
        (const __nv_bfloat16*)pghi, (const __nv_bfloat16*)pglo,
        (const __nv_bfloat16*)pffouthi, (const __nv_bfloat16*)pffoutlo,
        (float*)ph, BB*CDIM, ATT, FFN);

    // ---- final ----
    final_kernel<<<BB*CDIM, 256>>>(out_w, (const float*)po, (const float*)ph, out);
}

// round 4
// speedup vs baseline: 1.7436x; 1.0008x over previous
#include <cuda_runtime.h>
#include <cuda_bf16.h>
#include <cstdint>
#include <math.h>

// ---------------- problem constants ----------------
#define HNUM 16
#define CDIM 4096
#define HD 64
#define BB 4
#define SS 256
#define DIN 1024
#define ATT 1024
#define RR 256
#define CRN 1024
#define SCN 2048
#define FFN 3072
#define EPSV 1e-5f

// ---------------- device scratch (no allocations allowed) ----------------
__device__ __align__(16) float g_q[HNUM*CDIM*HD];
__device__ __align__(16) float g_qdet[HNUM*CDIM*HD];
__device__ __align__(16) float g_qr[HNUM*RR*HD];
__device__ __align__(16) float g_kvraw[BB*SS*2*ATT];
__device__ __align__(16) float g_k[BB*HNUM*SS*HD];
__device__ __align__(16) float g_v[BB*HNUM*SS*HD];
__device__ __align__(16) float g_o[BB*CDIM*ATT];
__device__ __align__(16) float g_f[(size_t)BB*CDIM*2*FFN];
__device__ __align__(16) float g_h[BB*CDIM*ATT];

// bf16 split buffers
__device__ __align__(16) __nv_bfloat16 g_xhi[BB*SS*DIN],        g_xlo[BB*SS*DIN];
__device__ __align__(16) __nv_bfloat16 g_kvwhi[2*ATT*DIN],      g_kvwlo[2*ATT*DIN];
__device__ __align__(16) __nv_bfloat16 g_lnhi[BB*CDIM*ATT],     g_lnlo[BB*CDIM*ATT];
__device__ __align__(16) __nv_bfloat16 g_ffinhi[2*FFN*ATT],     g_ffinlo[2*FFN*ATT];
__device__ __align__(16) __nv_bfloat16 g_ghi[(size_t)BB*CDIM*FFN], g_glo[(size_t)BB*CDIM*FFN];
__device__ __align__(16) __nv_bfloat16 g_ffouthi[ATT*FFN],      g_ffoutlo[ATT*FFN];

__device__ __forceinline__ float warp_sum(float v){
    #pragma unroll
    for (int o = 16; o; o >>= 1) v += __shfl_xor_sync(0xffffffffu, v, o);
    return v;
}
__device__ __forceinline__ float warp_max(float v){
    #pragma unroll
    for (int o = 16; o; o >>= 1) v = fmaxf(v, __shfl_xor_sync(0xffffffffu, v, o));
    return v;
}

// ---------------- generic float4 copy ----------------
__global__ void copy4_kernel(const float4* __restrict__ src, float4* __restrict__ dst, int n4){
    int i = blockIdx.x * blockDim.x + threadIdx.x;
    if (i < n4) dst[i] = src[i];
}

// ---------------- fp32 -> (hi, lo) bf16 split ----------------
__global__ void split_kernel(const float4* __restrict__ in, __nv_bfloat16* __restrict__ hi,
                             __nv_bfloat16* __restrict__ lo, int n4){
    int i = blockIdx.x * blockDim.x + threadIdx.x;
    if (i >= n4) return;
    float4 v = in[i];
    float vv[4] = {v.x, v.y, v.z, v.w};
    __nv_bfloat16 h[4], l[4];
    #pragma unroll
    for (int j = 0; j < 4; j++){
        h[j] = __float2bfloat16(vv[j]);
        l[j] = __float2bfloat16(vv[j] - __bfloat162float(h[j]));
    }
    *(uint2*)&hi[(size_t)i*4] = *(uint2*)h;
    *(uint2*)&lo[(size_t)i*4] = *(uint2*)l;
}

// ---------------- rmsnorm over rows of 64 (one warp per row) ----------------
__global__ void rms64_kernel(const float* __restrict__ in, float* __restrict__ out){
    int row = blockIdx.x, t = threadIdx.x;
    float2 v = ((const float2*)(in + (size_t)row*64))[t];
    float ss = v.x*v.x + v.y*v.y;
    ss = warp_sum(ss);
    float sc = rsqrtf(ss*(1.f/64.f) + EPSV);
    ((float2*)(out + (size_t)row*64))[t] = make_float2(v.x*sc, v.y*sc);
}

// ---------------- scatter-add ----------------
__global__ void scatter_kernel(const int* __restrict__ srcidx, const int* __restrict__ dstidx,
                               const float* __restrict__ w, const float* __restrict__ src,
                               float* __restrict__ dst, int nper, int src_rows){
    int j = blockIdx.x % nper;
    int h = blockIdx.x / nper;
    int r = srcidx[j];
    int c = dstidx[j];
    float ww = w[(size_t)h*nper + j];
    int t = threadIdx.x;  // 64
    atomicAdd(&dst[((size_t)h*CDIM + c)*64 + t], src[((size_t)h*src_rows + r)*64 + t] * ww);
}

// ---------------- split kv, rmsnorm k ----------------
__global__ void kvsplit_kernel(const float* __restrict__ kvraw, float* __restrict__ kout,
                               float* __restrict__ vout){
    int bid = blockIdx.x;               // (b*16+h)*256+s
    int t = threadIdx.x;                // 32
    int b = bid >> 12, h = (bid >> 8) & 15, s = bid & 255;
    size_t rowoff = ((size_t)(b*SS + s))*2048 + h*64;
    float2 kv = ((const float2*)(kvraw + rowoff))[t];
    float2 vv = ((const float2*)(kvraw + rowoff + 1024))[t];
    float ss = kv.x*kv.x + kv.y*kv.y;
    ss = warp_sum(ss);
    float sc = rsqrtf(ss*(1.f/64.f) + EPSV);
    ((float2*)(kout + (size_t)bid*64))[t] = make_float2(kv.x*sc, kv.y*sc);
    ((float2*)(vout + (size_t)bid*64))[t] = vv;
}

// ---------------- split-bf16 tensor-core GEMM (pipelined) ----------------
// C[M,N] = A[M,K] @ B[N,K]^T; A,B as (hi,lo) bf16; D = Ahi*Bhi + Ahi*Blo + Alo*Bhi
#define GR 40              // SMEM row stride in bf16 (80 bytes; conflict-free for ldmatrix)
#define BUF_BYTES (128*GR*2)   // 10240 bytes per (buffer, stage)
#define GEMM_SMEM (2*4*BUF_BYTES)  // 81920

__device__ __forceinline__ void mma16816(float* d, const unsigned int* a, const unsigned int* b){
    asm volatile(
        "mma.sync.aligned.m16n8k16.row.col.f32.bf16.bf16.f32 "
        "{%0,%1,%2,%3}, {%4,%5,%6,%7}, {%8,%9}, {%0,%1,%2,%3};\n"
        : "+f"(d[0]), "+f"(d[1]), "+f"(d[2]), "+f"(d[3])
        : "r"(a[0]), "r"(a[1]), "r"(a[2]), "r"(a[3]), "r"(b[0]), "r"(b[1]));
}

__device__ __forceinline__ void ldsm_x4(unsigned int& r0, unsigned int& r1,
                                        unsigned int& r2, unsigned int& r3, unsigned int addr){
    asm volatile("ldmatrix.sync.aligned.m8n8.x4.shared.b16 {%0,%1,%2,%3}, [%4];"
                 : "=r"(r0), "=r"(r1), "=r"(r2), "=r"(r3) : "r"(addr));
}

__device__ __forceinline__ void cpasync16(unsigned int saddr, const void* g){
    asm volatile("cp.async.cg.shared.global [%0], [%1], 16;" :: "r"(saddr), "l"(g));
}

__global__ void __launch_bounds__(256) gemm_nt_split(
    const __nv_bfloat16* __restrict__ Ahi, const __nv_bfloat16* __restrict__ Alo,
    const __nv_bfloat16* __restrict__ Bhi, const __nv_bfloat16* __restrict__ Blo,
    float* __restrict__ C, int M, int N, int K)
{
    extern __shared__ __nv_bfloat16 smem[];
    const int tid = threadIdx.x;
    const int bm = blockIdx.y << 7, bn = blockIdx.x << 7;
    const int warp = tid >> 5, lane = tid & 31;
    const int g = lane >> 2, tg = lane & 3;
    const int wm = (warp >> 1) << 5;   // 0,32,64,96
    const int wn = (warp & 1) << 6;    // 0,64
    float acc[2][8][4] = {};

    unsigned int sbase = (unsigned int)__cvta_generic_to_shared(smem);

    const __nv_bfloat16* gp0 = Ahi + (size_t)bm*K;
    const __nv_bfloat16* gp1 = Alo + (size_t)bm*K;
    const __nv_bfloat16* gp2 = Bhi + (size_t)bn*K;
    const __nv_bfloat16* gp3 = Blo + (size_t)bn*K;

    const int lr = tid >> 2;             // 0..63
    const int lc = (tid & 3) << 3;       // 0,8,16,24 (bf16 col)

    auto load_stage = [&](int k0, int s){
        unsigned int sb = sbase + s*4*BUF_BYTES;
        #pragma unroll
        for (int half = 0; half < 2; half++){
            int r = lr + (half << 6);
            size_t go = (size_t)r*K + k0 + lc;
            unsigned int so = (unsigned int)(r*GR + lc)*2;
            cpasync16(sb + 0*BUF_BYTES + so, gp0 + go);
            cpasync16(sb + 1*BUF_BYTES + so, gp1 + go);
            cpasync16(sb + 2*BUF_BYTES + so, gp2 + go);
            cpasync16(sb + 3*BUF_BYTES + so, gp3 + go);
        }
        asm volatile("cp.async.commit_group;");
    };

    load_stage(0, 0);
    const int nIt = K >> 5;
    for (int it = 0; it < nIt; it++){
        int s = it & 1;
        if (it + 1 < nIt){
            load_stage((it + 1) << 5, s ^ 1);
            asm volatile("cp.async.wait_group 1;");
        } else {
            asm volatile("cp.async.wait_group 0;");
        }
        __syncthreads();

        unsigned int sAh = sbase + (s*4 + 0)*BUF_BYTES;
        unsigned int sAl = sbase + (s*4 + 1)*BUF_BYTES;
        unsigned int sBh = sbase + (s*4 + 2)*BUF_BYTES;
        unsigned int sBl = sbase + (s*4 + 3)*BUF_BYTES;

        #pragma unroll
        for (int kg = 0; kg < 2; kg++){
            // A fragments: lanes 0-15 rows (wm+lane&15) kbyte kg*32; lanes 16-31 same rows +16B
            unsigned int ah[2][4], al[2][4];
            unsigned int aoff = (unsigned int)((wm + (lane & 15))*80 + kg*32 + ((lane >> 4) << 4));
            ldsm_x4(ah[0][0], ah[0][1], ah[0][2], ah[0][3], sAh + aoff);
            ldsm_x4(ah[1][0], ah[1][1], ah[1][2], ah[1][3], sAh + aoff + 16*80);
            ldsm_x4(al[0][0], al[0][1], al[0][2], al[0][3], sAl + aoff);
            ldsm_x4(al[1][0], al[1][1], al[1][2], al[1][3], sAl + aoff + 16*80);
            #pragma unroll
            for (int np = 0; np < 4; np++){
                // B pair: covers n-tiles np*2, np*2+1 (rows wn+np*16 .. +15)
                unsigned int boff = (unsigned int)(
                    (wn + np*16 + (lane & 7) + ((lane >> 4) << 3))*80
                    + kg*32 + (((lane >> 3) & 1) << 4));
                unsigned int bh[4], bl[4];
                ldsm_x4(bh[0], bh[1], bh[2], bh[3], sBh + boff);
                ldsm_x4(bl[0], bl[1], bl[2], bl[3], sBl + boff);
                #pragma unroll
                for (int mt = 0; mt < 2; mt++){
                    mma16816(acc[mt][np*2],     ah[mt], bh);
                    mma16816(acc[mt][np*2],     ah[mt], bl);
                    mma16816(acc[mt][np*2],     al[mt], bh);
                    mma16816(acc[mt][np*2 + 1], ah[mt], bh + 2);
                    mma16816(acc[mt][np*2 + 1], ah[mt], bl + 2);
                    mma16816(acc[mt][np*2 + 1], al[mt], bh + 2);
                }
            }
        }
        __syncthreads();
    }

    #pragma unroll
    for (int mt = 0; mt < 2; mt++){
        #pragma unroll
        for (int nt = 0; nt < 8; nt++){
            size_t row0 = (size_t)bm + wm + (mt << 4) + g;
            int col = bn + wn + (nt << 3) + (tg << 1);
            *(float2*)&C[row0*N + col]      = make_float2(acc[mt][nt][0], acc[mt][nt][1]);
            *(float2*)&C[(row0+8)*N + col]  = make_float2(acc[mt][nt][2], acc[mt][nt][3]);
        }
    }
}

// ---------------- attention: one block per (b*h, c-tile of 256) ----------------
#define SROW 68
__global__ void __launch_bounds__(256) attn_kernel(const float* __restrict__ q,
                                                   const float* __restrict__ k,
                                                   const float* __restrict__ v,
                                                   float* __restrict__ o){
    extern __shared__ float sm[];
    float* ks = sm;
    float* vs = ks + 256*SROW;
    float* qs = vs + 256*SROW;
    float* at = qs + 64;
    float* op = at + 256;
    float* rd = op + 256;
    int tid = threadIdx.x;
    int bh = blockIdx.x;
    int b = bh >> 4, h = bh & 15;
    size_t base = (size_t)bh * SS * HD;
    for (int i = tid; i < SS*16; i += 256){
        int s = i >> 4, c4 = (i & 15) << 2;
        float4 kk = *(const float4*)(k + base + (size_t)s*64 + c4);
        float4 vv = *(const float4*)(v + base + (size_t)s*64 + c4);
        ks[s*SROW+c4] = kk.x; ks[s*SROW+c4+1] = kk.y; ks[s*SROW+c4+2] = kk.z; ks[s*SROW+c4+3] = kk.w;
        vs[s*SROW+c4] = vv.x; vs[s*SROW+c4+1] = vv.y; vs[s*SROW+c4+2] = vv.z; vs[s*SROW+c4+3] = vv.w;
    }
    __syncthreads();
    int c0 = blockIdx.y << 8;
    for (int c = 0; c < 256; c++){
        int cc = c0 + c;
        if (tid < 16){
            float4 qv = *(const float4*)(q + ((size_t)h*CDIM + cc)*64 + (tid << 2));
            qs[tid*4] = qv.x; qs[tid*4+1] = qv.y; qs[tid*4+2] = qv.z; qs[tid*4+3] = qv.w;
        }
        __syncthreads();
        float sc = 0.f;
        #pragma unroll
        for (int e = 0; e < 64; e += 4){
            float4 kk = *(float4*)&ks[tid*SROW + e];
            sc += kk.x*qs[e] + kk.y*qs[e+1] + kk.z*qs[e+2] + kk.w*qs[e+3];
        }
        sc *= 0.125f;
        float wmax = warp_max(sc);
        if ((tid & 31) == 0) rd[tid >> 5] = wmax;
        __syncthreads();
        float bmax = rd[0];
        #pragma unroll
        for (int i = 1; i < 8; i++) bmax = fmaxf(bmax, rd[i]);
        float ex = __expf(sc - bmax);
        at[tid] = ex;
        float wsum = warp_sum(ex);
        if ((tid & 31) == 0) rd[8 + (tid >> 5)] = wsum;
        __syncthreads();
        float bsum = 0.f;
        #pragma unroll
        for (int i = 0; i < 8; i++) bsum += rd[8 + i];
        float inv = 1.f / bsum;
        int e = tid & 63, ch = tid >> 6;
        float acc = 0.f;
        #pragma unroll 8
        for (int i = 0; i < 64; i++){
            int s = (ch << 6) + i;
            acc = fmaf(at[s], vs[s*SROW + e], acc);
        }
        op[tid] = acc;
        __syncthreads();
        if (tid < 64){
            float oo = (op[tid] + op[64+tid] + op[128+tid] + op[192+tid]) * inv;
            o[((size_t)b*CDIM + cc)*ATT + h*64 + tid] = oo;
        }
        __syncthreads();
    }
}

// ---------------- layernorm rows of 1024, fused bf16 split output ----------------
__global__ void __launch_bounds__(256) ln_split_kernel(const float* __restrict__ gamma,
                                                       const float* __restrict__ beta,
                                                       const float* __restrict__ in,
                                                       __nv_bfloat16* __restrict__ hi,
                                                       __nv_bfloat16* __restrict__ lo){
    __shared__ float rs[8], rq[8];
    int row = blockIdx.x, tid = threadIdx.x;
    float4 v = ((const float4*)(in + (size_t)row*ATT))[tid];
    float s = v.x+v.y+v.z+v.w;
    float q = v.x*v.x+v.y*v.y+v.z*v.z+v.w*v.w;
    s = warp_sum(s); q = warp_sum(q);
    if ((tid & 31) == 0){ rs[tid>>5] = s; rq[tid>>5] = q; }
    __syncthreads();
    float ts = 0.f, tq = 0.f;
    #pragma unroll
    for (int i = 0; i < 8; i++){ ts += rs[i]; tq += rq[i]; }
    float mu = ts * (1.f/1024.f);
    float var = tq * (1.f/1024.f) - mu*mu;
    float rr = rsqrtf(var + EPSV);
    float4 g4 = ((const float4*)gamma)[tid];
    float4 b4 = ((const float4*)beta)[tid];
    float ov[4];
    ov[0] = (v.x-mu)*rr*g4.x + b4.x;
    ov[1] = (v.y-mu)*rr*g4.y + b4.y;
    ov[2] = (v.z-mu)*rr*g4.z + b4.z;
    ov[3] = (v.w-mu)*rr*g4.w + b4.w;
    __nv_bfloat16 h[4], l[4];
    #pragma unroll
    for (int j = 0; j < 4; j++){
        h[j] = __float2bfloat16(ov[j]);
        l[j] = __float2bfloat16(ov[j] - __bfloat162float(h[j]));
    }
    size_t off = (size_t)row*ATT + tid*4;
    *(uint2*)&hi[off] = *(uint2*)h;
    *(uint2*)&lo[off] = *(uint2*)l;
}

// ---------------- gate: g = silu(f1)*f2, fused bf16 split output ----------------
__global__ void gate_split_kernel(const float* __restrict__ f,
                                  __nv_bfloat16* __restrict__ ghi,
                                  __nv_bfloat16* __restrict__ glo, int n4){
    int i = blockIdx.x * blockDim.x + threadIdx.x;
    if (i >= n4) return;
    size_t e = (size_t)i*4;
    size_t m = e / FFN;
    int j = (int)(e - m*FFN);
    float4 f1 = *(const float4*)&f[m*2*FFN + j];
    float4 f2 = *(const float4*)&f[m*2*FFN + FFN + j];
    float gg[4];
    gg[0] = f1.x / (1.f + __expf(-f1.x)) * f2.x;
    gg[1] = f1.y / (1.f + __expf(-f1.y)) * f2.y;
    gg[2] = f1.z / (1.f + __expf(-f1.z)) * f2.z;
    gg[3] = f1.w / (1.f + __expf(-f1.w)) * f2.w;
    __nv_bfloat16 h[4], l[4];
    #pragma unroll
    for (int q = 0; q < 4; q++){
        h[q] = __float2bfloat16(gg[q]);
        l[q] = __float2bfloat16(gg[q] - __bfloat162float(h[q]));
    }
    *(uint2*)&ghi[e] = *(uint2*)h;
    *(uint2*)&glo[e] = *(uint2*)l;
}

// ---------------- final: z = o+h; y = z @ out_w[c]; out = silu(y0)*y1 ----------------
__global__ void __launch_bounds__(256) final_kernel(const float* __restrict__ ow,
                                                    const float* __restrict__ o,
                                                    const float* __restrict__ h,
                                                    float* __restrict__ out){
    __shared__ float r0[8], r1[8];
    int row = blockIdx.x, tid = threadIdx.x;
    int c = row & (CDIM-1);
    const float2* w = (const float2*)(ow + (size_t)c*2048);
    float a0 = 0.f, a1 = 0.f;
    #pragma unroll
    for (int it = 0; it < 4; it++){
        int a = tid + it*256;
        float z = o[(size_t)row*ATT + a] + h[(size_t)row*ATT + a];
        float2 ww = w[a];
        a0 = fmaf(z, ww.x, a0);
        a1 = fmaf(z, ww.y, a1);
    }
    a0 = warp_sum(a0); a1 = warp_sum(a1);
    if ((tid & 31) == 0){ r0[tid>>5] = a0; r1[tid>>5] = a1; }
    __syncthreads();
    if (tid == 0){
        float y0 = 0.f, y1 = 0.f;
        #pragma unroll
        for (int i = 0; i < 8; i++){ y0 += r0[i]; y1 += r1[i]; }
        out[row] = y0 / (1.f + __expf(-y0)) * y1;
    }
}

// ---------------- launch ----------------
extern "C" void kernel_launch(void* const* d_in, const int* in_sizes, int n_in,
                              void* d_out, int out_size){
    const float* x        = (const float*)d_in[0];
    const float* cls      = (const float*)d_in[1];
    const float* roots    = (const float*)d_in[2];
    const float* cr_w     = (const float*)d_in[3];
    const float* cc_w     = (const float*)d_in[4];
    const float* kv_w     = (const float*)d_in[5];
    const float* ln_gamma = (const float*)d_in[6];
    const float* ln_beta  = (const float*)d_in[7];
    const float* ff_in_w  = (const float*)d_in[8];
    const float* ff_out_w = (const float*)d_in[9];
    const float* out_w    = (const float*)d_in[10];
    const int*   cr_idx   = (const int*)d_in[11];
    const int*   cc_idx   = (const int*)d_in[12];
    float* out = (float*)d_out;

    void *pq, *pqdet, *pqr, *pkvraw, *pk, *pv, *po, *pf, *ph;
    void *pxhi, *pxlo, *pkvwhi, *pkvwlo, *plnhi, *plnlo, *pffinhi, *pffinlo;
    void *pghi, *pglo, *pffouthi, *pffoutlo;
    cudaGetSymbolAddress(&pq, g_q);
    cudaGetSymbolAddress(&pqdet, g_qdet);
    cudaGetSymbolAddress(&pqr, g_qr);
    cudaGetSymbolAddress(&pkvraw, g_kvraw);
    cudaGetSymbolAddress(&pk, g_k);
    cudaGetSymbolAddress(&pv, g_v);
    cudaGetSymbolAddress(&po, g_o);
    cudaGetSymbolAddress(&pf, g_f);
    cudaGetSymbolAddress(&ph, g_h);
    cudaGetSymbolAddress(&pxhi, g_xhi);       cudaGetSymbolAddress(&pxlo, g_xlo);
    cudaGetSymbolAddress(&pkvwhi, g_kvwhi);   cudaGetSymbolAddress(&pkvwlo, g_kvwlo);
    cudaGetSymbolAddress(&plnhi, g_lnhi);     cudaGetSymbolAddress(&plnlo, g_lnlo);
    cudaGetSymbolAddress(&pffinhi, g_ffinhi); cudaGetSymbolAddress(&pffinlo, g_ffinlo);
    cudaGetSymbolAddress(&pghi, g_ghi);       cudaGetSymbolAddress(&pglo, g_glo);
    cudaGetSymbolAddress(&pffouthi, g_ffouthi); cudaGetSymbolAddress(&pffoutlo, g_ffoutlo);

    int attn_smem = (2*256*SROW + 64 + 256 + 256 + 16) * 4;
    cudaFuncSetAttribute(attn_kernel, cudaFuncAttributeMaxDynamicSharedMemorySize, attn_smem);
    cudaFuncSetAttribute(gemm_nt_split, cudaFuncAttributeMaxDynamicSharedMemorySize, GEMM_SMEM);

    // ---- q preparation ----
    copy4_kernel<<<(HNUM*CDIM*HD/4 + 255)/256, 256>>>((const float4*)cls, (float4*)pq, HNUM*CDIM*HD/4);
    rms64_kernel<<<HNUM*RR, 32>>>(roots, (float*)pqr);
    scatter_kernel<<<HNUM*CRN, 64>>>(cr_idx, cr_idx + CRN, cr_w, (const float*)pqr, (float*)pq, CRN, RR);
    copy4_kernel<<<(HNUM*CDIM*HD/4 + 255)/256, 256>>>((const float4*)pq, (float4*)pqdet, HNUM*CDIM*HD/4);
    scatter_kernel<<<HNUM*SCN, 64>>>(cc_idx, cc_idx + SCN, cc_w, (const float*)pqdet, (float*)pq, SCN, CDIM);
    rms64_kernel<<<HNUM*CDIM, 32>>>((const float*)pq, (float*)pq);

    // ---- kv = x @ kv_w^T on tensor cores ----
    split_kernel<<<(BB*SS*DIN/4 + 255)/256, 256>>>((const float4*)x, (__nv_bfloat16*)pxhi,
                                                   (__nv_bfloat16*)pxlo, BB*SS*DIN/4);
    split_kernel<<<(2*ATT*DIN/4 + 255)/256, 256>>>((const float4*)kv_w, (__nv_bfloat16*)pkvwhi,
                                                   (__nv_bfloat16*)pkvwlo, 2*ATT*DIN/4);
    gemm_nt_split<<<dim3(2*ATT/128, BB*SS/128), 256, GEMM_SMEM>>>(
        (const __nv_bfloat16*)pxhi, (const __nv_bfloat16*)pxlo,
        (const __nv_bfloat16*)pkvwhi, (const __nv_bfloat16*)pkvwlo,
        (float*)pkvraw, BB*SS, 2*ATT, DIN);
    kvsplit_kernel<<<BB*HNUM*SS, 32>>>((const float*)pkvraw, (float*)pk, (float*)pv);

    // ---- attention ----
    attn_kernel<<<dim3(BB*HNUM, CDIM/256), 256, attn_smem>>>((const float*)pq, (const float*)pk,
                                                             (const float*)pv, (float*)po);

    // ---- layernorm + split ----
    ln_split_kernel<<<BB*CDIM, 256>>>(ln_gamma, ln_beta, (const float*)po,
                                      (__nv_bfloat16*)plnhi, (__nv_bfloat16*)plnlo);

    // ---- FF1: f = ln @ ff_in_w^T (16384 x 6144 x 1024) ----
    split_kernel<<<(2*FFN*ATT/4 + 255)/256, 256>>>((const float4*)ff_in_w, (__nv_bfloat16*)pffinhi,
                                                   (__nv_bfloat16*)pffinlo, 2*FFN*ATT/4);
    gemm_nt_split<<<dim3(2*FFN/128, BB*CDIM/128), 256, GEMM_SMEM>>>(
        (const __nv_bfloat16*)plnhi, (const __nv_bfloat16*)plnlo,
        (const __nv_bfloat16*)pffinhi, (const __nv_bfloat16*)pffinlo,
        (float*)pf, BB*CDIM, 2*FFN, ATT);

    // ---- gate + split ----
    {
        int n4 = BB*CDIM*FFN/4;
        gate_split_kernel<<<(n4 + 255)/256, 256>>>((const float*)pf, (__nv_bfloat16*)pghi,
                                                   (__nv_bfloat16*)pglo, n4);
    }

    // ---- FF2: h = gate @ ff_out_w^T (16384 x 1024 x 3072) ----
    split_kernel<<<(ATT*FFN/4 + 255)/256, 256>>>((const float4*)ff_out_w, (__nv_bfloat16*)pffouthi,
                                                 (__nv_bfloat16*)pffoutlo, ATT*FFN/4);
    gemm_nt_split<<<dim3(ATT/128, BB*CDIM/128), 256, GEMM_SMEM>>>(
        (const __nv_bfloat16*)pghi, (const __nv_bfloat16*)pglo,
        (const __nv_bfloat16*)pffouthi, (const __nv_bfloat16*)pffoutlo,
        (float*)ph, BB*CDIM, ATT, FFN);

    // ---- final ----
    final_kernel<<<BB*CDIM, 256>>>(out_w, (const float*)po, (const float*)ph, out);
}

// round 6
// speedup vs baseline: 2.2232x; 1.2751x over previous
#include <cuda_runtime.h>
#include <cuda_fp16.h>
#include <cuda_bf16.h>
#include <cstdint>
#include <math.h>

// ---------------- problem constants ----------------
#define HNUM 16
#define CDIM 4096
#define HD 64
#define BB 4
#define SS 256
#define DIN 1024
#define ATT 1024
#define RR 256
#define CRN 1024
#define SCN 2048
#define FFN 3072
#define EPSV 1e-5f

// ---------------- device scratch (no allocations allowed) ----------------
__device__ __align__(16) float g_q[HNUM*CDIM*HD];
__device__ __align__(16) float g_qdet[HNUM*CDIM*HD];
__device__ __align__(16) float g_qr[HNUM*RR*HD];
__device__ __align__(16) float g_kvraw[BB*SS*2*ATT];
__device__ __align__(16) float g_k[BB*HNUM*SS*HD];
__device__ __align__(16) float g_v[BB*HNUM*SS*HD];
__device__ __align__(16) float g_o[BB*CDIM*ATT];
__device__ __align__(16) float g_f[(size_t)BB*CDIM*2*FFN];
__device__ __align__(16) float g_h[BB*CDIM*ATT];

// fp16 split buffers: A-side (hi,lo), B-side (weights) single fp16
__device__ __align__(16) __half g_xhi[BB*SS*DIN],        g_xlo[BB*SS*DIN];
__device__ __align__(16) __half g_kvwh[2*ATT*DIN];
__device__ __align__(16) __half g_lnhi[BB*CDIM*ATT],     g_lnlo[BB*CDIM*ATT];
__device__ __align__(16) __half g_ffinh[2*FFN*ATT];
__device__ __align__(16) __half g_ghi[(size_t)BB*CDIM*FFN], g_glo[(size_t)BB*CDIM*FFN];
__device__ __align__(16) __half g_ffouth[ATT*FFN];

__device__ __forceinline__ float warp_sum(float v){
    #pragma unroll
    for (int o = 16; o; o >>= 1) v += __shfl_xor_sync(0xffffffffu, v, o);
    return v;
}
__device__ __forceinline__ float warp_max(float v){
    #pragma unroll
    for (int o = 16; o; o >>= 1) v = fmaxf(v, __shfl_xor_sync(0xffffffffu, v, o));
    return v;
}

// ---------------- generic float4 copy ----------------
__global__ void copy4_kernel(const float4* __restrict__ src, float4* __restrict__ dst, int n4){
    int i = blockIdx.x * blockDim.x + threadIdx.x;
    if (i < n4) dst[i] = src[i];
}

// ---------------- fp32 -> (hi, lo) fp16 split ----------------
__global__ void split_kernel(const float4* __restrict__ in, __half* __restrict__ hi,
                             __half* __restrict__ lo, int n4){
    int i = blockIdx.x * blockDim.x + threadIdx.x;
    if (i >= n4) return;
    float4 v = in[i];
    float vv[4] = {v.x, v.y, v.z, v.w};
    __half h[4], l[4];
    #pragma unroll
    for (int j = 0; j < 4; j++){
        h[j] = __float2half(vv[j]);
        l[j] = __float2half(vv[j] - __half2float(h[j]));
    }
    *(uint2*)&hi[(size_t)i*4] = *(uint2*)h;
    *(uint2*)&lo[(size_t)i*4] = *(uint2*)l;
}

// ---------------- fp32 -> fp16 convert (weights) ----------------
__global__ void conv_half_kernel(const float4* __restrict__ in, __half* __restrict__ out, int n4){
    int i = blockIdx.x * blockDim.x + threadIdx.x;
    if (i >= n4) return;
    float4 v = in[i];
    __half h[4] = {__float2half(v.x), __float2half(v.y), __float2half(v.z), __float2half(v.w)};
    *(uint2*)&out[(size_t)i*4] = *(uint2*)h;
}

// ---------------- rmsnorm over rows of 64 (one warp per row) ----------------
__global__ void rms64_kernel(const float* __restrict__ in, float* __restrict__ out){
    int row = blockIdx.x, t = threadIdx.x;
    float2 v = ((const float2*)(in + (size_t)row*64))[t];
    float ss = v.x*v.x + v.y*v.y;
    ss = warp_sum(ss);
    float sc = rsqrtf(ss*(1.f/64.f) + EPSV);
    ((float2*)(out + (size_t)row*64))[t] = make_float2(v.x*sc, v.y*sc);
}

// ---------------- scatter-add ----------------
__global__ void scatter_kernel(const int* __restrict__ srcidx, const int* __restrict__ dstidx,
                               const float* __restrict__ w, const float* __restrict__ src,
                               float* __restrict__ dst, int nper, int src_rows){
    int j = blockIdx.x % nper;
    int h = blockIdx.x / nper;
    int r = srcidx[j];
    int c = dstidx[j];
    float ww = w[(size_t)h*nper + j];
    int t = threadIdx.x;  // 64
    atomicAdd(&dst[((size_t)h*CDIM + c)*64 + t], src[((size_t)h*src_rows + r)*64 + t] * ww);
}

// ---------------- split kv, rmsnorm k ----------------
__global__ void kvsplit_kernel(const float* __restrict__ kvraw, float* __restrict__ kout,
                               float* __restrict__ vout){
    int bid = blockIdx.x;               // (b*16+h)*256+s
    int t = threadIdx.x;                // 32
    int b = bid >> 12, h = (bid >> 8) & 15, s = bid & 255;
    size_t rowoff = ((size_t)(b*SS + s))*2048 + h*64;
    float2 kv = ((const float2*)(kvraw + rowoff))[t];
    float2 vv = ((const float2*)(kvraw + rowoff + 1024))[t];
    float ss = kv.x*kv.x + kv.y*kv.y;
    ss = warp_sum(ss);
    float sc = rsqrtf(ss*(1.f/64.f) + EPSV);
    ((float2*)(kout + (size_t)bid*64))[t] = make_float2(kv.x*sc, kv.y*sc);
    ((float2*)(vout + (size_t)bid*64))[t] = vv;
}

// ---------------- split-fp16 tensor-core GEMM (pipelined) ----------------
// C[M,N] = A[M,K] @ B[N,K]^T; A as (hi,lo) fp16, B fp16; D = Ahi*B + Alo*B (fp32 accum)
#define GR 40                        // SMEM row stride in fp16 (80 bytes; ldmatrix conflict-free)
#define BUF_BYTES (128*GR*2)         // 10240 bytes per (buffer, stage)
#define GEMM_SMEM (2*3*BUF_BYTES)    // 61440

__device__ __forceinline__ void mma16816(float* d, const unsigned int* a, const unsigned int* b){
    asm volatile(
        "mma.sync.aligned.m16n8k16.row.col.f32.f16.f16.f32 "
        "{%0,%1,%2,%3}, {%4,%5,%6,%7}, {%8,%9}, {%0,%1,%2,%3};\n"
        : "+f"(d[0]), "+f"(d[1]), "+f"(d[2]), "+f"(d[3])
        : "r"(a[0]), "r"(a[1]), "r"(a[2]), "r"(a[3]), "r"(b[0]), "r"(b[1]));
}

__device__ __forceinline__ void ldsm_x4(unsigned int& r0, unsigned int& r1,
                                        unsigned int& r2, unsigned int& r3, unsigned int addr){
    asm volatile("ldmatrix.sync.aligned.m8n8.x4.shared.b16 {%0,%1,%2,%3}, [%4];"
                 : "=r"(r0), "=r"(r1), "=r"(r2), "=r"(r3) : "r"(addr));
}

__device__ __forceinline__ void cpasync16(unsigned int saddr, const void* g){
    asm volatile("cp.async.cg.shared.global [%0], [%1], 16;" :: "r"(saddr), "l"(g));
}

__global__ void __launch_bounds__(256) gemm_nt_split(
    const __half* __restrict__ Ahi, const __half* __restrict__ Alo,
    const __half* __restrict__ Bh,
    float* __restrict__ C, int M, int N, int K)
{
    extern __shared__ __half smem[];
    const int tid = threadIdx.x;
    const int bm = blockIdx.y << 7, bn = blockIdx.x << 7;
    const int warp = tid >> 5, lane = tid & 31;
    const int g = lane >> 2, tg = lane & 3;
    const int wm = (warp >> 1) << 5;   // 0,32,64,96
    const int wn = (warp & 1) << 6;    // 0,64
    float acc[2][8][4] = {};

    unsigned int sbase = (unsigned int)__cvta_generic_to_shared(smem);

    const __half* gp0 = Ahi + (size_t)bm*K;
    const __half* gp1 = Alo + (size_t)bm*K;
    const __half* gp2 = Bh  + (size_t)bn*K;

    const int lr = tid >> 2;             // 0..63
    const int lc = (tid & 3) << 3;       // 0,8,16,24 (fp16 col)

    auto load_stage = [&](int k0, int s){
        unsigned int sb = sbase + s*3*BUF_BYTES;
        #pragma unroll
        for (int half_i = 0; half_i < 2; half_i++){
            int r = lr + (half_i << 6);
            size_t go = (size_t)r*K + k0 + lc;
            unsigned int so = (unsigned int)(r*GR + lc)*2;
            cpasync16(sb + 0*BUF_BYTES + so, gp0 + go);
            cpasync16(sb + 1*BUF_BYTES + so, gp1 + go);
            cpasync16(sb + 2*BUF_BYTES + so, gp2 + go);
        }
        asm volatile("cp.async.commit_group;");
    };

    load_stage(0, 0);
    const int nIt = K >> 5;
    for (int it = 0; it < nIt; it++){
        int s = it & 1;
        if (it + 1 < nIt){
            load_stage((it + 1) << 5, s ^ 1);
            asm volatile("cp.async.wait_group 1;");
        } else {
            asm volatile("cp.async.wait_group 0;");
        }
        __syncthreads();

        unsigned int sAh = sbase + (s*3 + 0)*BUF_BYTES;
        unsigned int sAl = sbase + (s*3 + 1)*BUF_BYTES;
        unsigned int sBh = sbase + (s*3 + 2)*BUF_BYTES;

        #pragma unroll
        for (int kg = 0; kg < 2; kg++){
            unsigned int ah[2][4], al[2][4];
            unsigned int aoff = (unsigned int)((wm + (lane & 15))*80 + kg*32 + ((lane >> 4) << 4));
            ldsm_x4(ah[0][0], ah[0][1], ah[0][2], ah[0][3], sAh + aoff);
            ldsm_x4(ah[1][0], ah[1][1], ah[1][2], ah[1][3], sAh + aoff + 16*80);
            ldsm_x4(al[0][0], al[0][1], al[0][2], al[0][3], sAl + aoff);
            ldsm_x4(al[1][0], al[1][1], al[1][2], al[1][3], sAl + aoff + 16*80);
            #pragma unroll
            for (int np = 0; np < 4; np++){
                unsigned int boff = (unsigned int)(
                    (wn + np*16 + (lane & 7) + ((lane >> 4) << 3))*80
                    + kg*32 + (((lane >> 3) & 1) << 4));
                unsigned int bh[4];
                ldsm_x4(bh[0], bh[1], bh[2], bh[3], sBh + boff);
                #pragma unroll
                for (int mt = 0; mt < 2; mt++){
                    mma16816(acc[mt][np*2],     ah[mt], bh);
                    mma16816(acc[mt][np*2],     al[mt], bh);
                    mma16816(acc[mt][np*2 + 1], ah[mt], bh + 2);
                    mma16816(acc[mt][np*2 + 1], al[mt], bh + 2);
                }
            }
        }
        __syncthreads();
    }

    #pragma unroll
    for (int mt = 0; mt < 2; mt++){
        #pragma unroll
        for (int nt = 0; nt < 8; nt++){
            size_t row0 = (size_t)bm + wm + (mt << 4) + g;
            int col = bn + wn + (nt << 3) + (tg << 1);
            *(float2*)&C[row0*N + col]      = make_float2(acc[mt][nt][0], acc[mt][nt][1]);
            *(float2*)&C[(row0+8)*N + col]  = make_float2(acc[mt][nt][2], acc[mt][nt][3]);
        }
    }
}

// ---------------- attention: one block per (b*h, c-tile of 256) ----------------
#define SROW 68
__global__ void __launch_bounds__(256) attn_kernel(const float* __restrict__ q,
                                                   const float* __restrict__ k,
                                                   const float* __restrict__ v,
                                                   float* __restrict__ o){
    extern __shared__ float sm[];
    float* ks = sm;
    float* vs = ks + 256*SROW;
    float* qs = vs + 256*SROW;
    float* at = qs + 64;
    float* op = at + 256;
    float* rd = op + 256;
    int tid = threadIdx.x;
    int bh = blockIdx.x;
    int b = bh >> 4, h = bh & 15;
    size_t base = (size_t)bh * SS * HD;
    for (int i = tid; i < SS*16; i += 256){
        int s = i >> 4, c4 = (i & 15) << 2;
        float4 kk = *(const float4*)(k + base + (size_t)s*64 + c4);
        float4 vv = *(const float4*)(v + base + (size_t)s*64 + c4);
        ks[s*SROW+c4] = kk.x; ks[s*SROW+c4+1] = kk.y; ks[s*SROW+c4+2] = kk.z; ks[s*SROW+c4+3] = kk.w;
        vs[s*SROW+c4] = vv.x; vs[s*SROW+c4+1] = vv.y; vs[s*SROW+c4+2] = vv.z; vs[s*SROW+c4+3] = vv.w;
    }
    __syncthreads();
    int c0 = blockIdx.y << 8;
    for (int c = 0; c < 256; c++){
        int cc = c0 + c;
        if (tid < 16){
            float4 qv = *(const float4*)(q + ((size_t)h*CDIM + cc)*64 + (tid << 2));
            qs[tid*4] = qv.x; qs[tid*4+1] = qv.y; qs[tid*4+2] = qv.z; qs[tid*4+3] = qv.w;
        }
        __syncthreads();
        float sc = 0.f;
        #pragma unroll
        for (int e = 0; e < 64; e += 4){
            float4 kk = *(float4*)&ks[tid*SROW + e];
            sc += kk.x*qs[e] + kk.y*qs[e+1] + kk.z*qs[e+2] + kk.w*qs[e+3];
        }
        sc *= 0.125f;
        float wmax = warp_max(sc);
        if ((tid & 31) == 0) rd[tid >> 5] = wmax;
        __syncthreads();
        float bmax = rd[0];
        #pragma unroll
        for (int i = 1; i < 8; i++) bmax = fmaxf(bmax, rd[i]);
        float ex = __expf(sc - bmax);
        at[tid] = ex;
        float wsum = warp_sum(ex);
        if ((tid & 31) == 0) rd[8 + (tid >> 5)] = wsum;
        __syncthreads();
        float bsum = 0.f;
        #pragma unroll
        for (int i = 0; i < 8; i++) bsum += rd[8 + i];
        float inv = 1.f / bsum;
        int e = tid & 63, ch = tid >> 6;
        float acc = 0.f;
        #pragma unroll 8
        for (int i = 0; i < 64; i++){
            int s = (ch << 6) + i;
            acc = fmaf(at[s], vs[s*SROW + e], acc);
        }
        op[tid] = acc;
        __syncthreads();
        if (tid < 64){
            float oo = (op[tid] + op[64+tid] + op[128+tid] + op[192+tid]) * inv;
            o[((size_t)b*CDIM + cc)*ATT + h*64 + tid] = oo;
        }
        __syncthreads();
    }
}

// ---------------- layernorm rows of 1024, fused fp16 split output ----------------
__global__ void __launch_bounds__(256) ln_split_kernel(const float* __restrict__ gamma,
                                                       const float* __restrict__ beta,
                                                       const float* __restrict__ in,
                                                       __half* __restrict__ hi,
                                                       __half* __restrict__ lo){
    __shared__ float rs[8], rq[8];
    int row = blockIdx.x, tid = threadIdx.x;
    float4 v = ((const float4*)(in + (size_t)row*ATT))[tid];
    float s = v.x+v.y+v.z+v.w;
    float q = v.x*v.x+v.y*v.y+v.z*v.z+v.w*v.w;
    s = warp_sum(s); q = warp_sum(q);
    if ((tid & 31) == 0){ rs[tid>>5] = s; rq[tid>>5] = q; }
    __syncthreads();
    float ts = 0.f, tq = 0.f;
    #pragma unroll
    for (int i = 0; i < 8; i++){ ts += rs[i]; tq += rq[i]; }
    float mu = ts * (1.f/1024.f);
    float var = tq * (1.f/1024.f) - mu*mu;
    float rr = rsqrtf(var + EPSV);
    float4 g4 = ((const float4*)gamma)[tid];
    float4 b4 = ((const float4*)beta)[tid];
    float ov[4];
    ov[0] = (v.x-mu)*rr*g4.x + b4.x;
    ov[1] = (v.y-mu)*rr*g4.y + b4.y;
    ov[2] = (v.z-mu)*rr*g4.z + b4.z;
    ov[3] = (v.w-mu)*rr*g4.w + b4.w;
    __half h[4], l[4];
    #pragma unroll
    for (int j = 0; j < 4; j++){
        h[j] = __float2half(ov[j]);
        l[j] = __float2half(ov[j] - __half2float(h[j]));
    }
    size_t off = (size_t)row*ATT + tid*4;
    *(uint2*)&hi[off] = *(uint2*)h;
    *(uint2*)&lo[off] = *(uint2*)l;
}

// ---------------- gate: g = silu(f1)*f2, fused fp16 split output ----------------
__global__ void gate_split_kernel(const float* __restrict__ f,
                                  __half* __restrict__ ghi,
                                  __half* __restrict__ glo, int n4){
    int i = blockIdx.x * blockDim.x + threadIdx.x;
    if (i >= n4) return;
    size_t e = (size_t)i*4;
    size_t m = e / FFN;
    int j = (int)(e - m*FFN);
    float4 f1 = *(const float4*)&f[m*2*FFN + j];
    float4 f2 = *(const float4*)&f[m*2*FFN + FFN + j];
    float gg[4];
    gg[0] = f1.x / (1.f + __expf(-f1.x)) * f2.x;
    gg[1] = f1.y / (1.f + __expf(-f1.y)) * f2.y;
    gg[2] = f1.z / (1.f + __expf(-f1.z)) * f2.z;
    gg[3] = f1.w / (1.f + __expf(-f1.w)) * f2.w;
    __half h[4], l[4];
    #pragma unroll
    for (int q = 0; q < 4; q++){
        h[q] = __float2half(gg[q]);
        l[q] = __float2half(gg[q] - __half2float(h[q]));
    }
    *(uint2*)&ghi[e] = *(uint2*)h;
    *(uint2*)&glo[e] = *(uint2*)l;
}

// ---------------- final: z = o+h; y = z @ out_w[c]; out = silu(y0)*y1 ----------------
__global__ void __launch_bounds__(256) final_kernel(const float* __restrict__ ow,
                                                    const float* __restrict__ o,
                                                    const float* __restrict__ h,
                                                    float* __restrict__ out){
    __shared__ float r0[8], r1[8];
    int row = blockIdx.x, tid = threadIdx.x;
    int c = row & (CDIM-1);
    const float2* w = (const float2*)(ow + (size_t)c*2048);
    float a0 = 0.f, a1 = 0.f;
    #pragma unroll
    for (int it = 0; it < 4; it++){
        int a = tid + it*256;
        float z = o[(size_t)row*ATT + a] + h[(size_t)row*ATT + a];
        float2 ww = w[a];
        a0 = fmaf(z, ww.x, a0);
        a1 = fmaf(z, ww.y, a1);
    }
    a0 = warp_sum(a0); a1 = warp_sum(a1);
    if ((tid & 31) == 0){ r0[tid>>5] = a0; r1[tid>>5] = a1; }
    __syncthreads();
    if (tid == 0){
        float y0 = 0.f, y1 = 0.f;
        #pragma unroll
        for (int i = 0; i < 8; i++){ y0 += r0[i]; y1 += r1[i]; }
        out[row] = y0 / (1.f + __expf(-y0)) * y1;
    }
}

// ---------------- launch ----------------
extern "C" void kernel_launch(void* const* d_in, const int* in_sizes, int n_in,
                              void* d_out, int out_size){
    const float* x        = (const float*)d_in[0];
    const float* cls      = (const float*)d_in[1];
    const float* roots    = (const float*)d_in[2];
    const float* cr_w     = (const float*)d_in[3];
    const float* cc_w     = (const float*)d_in[4];
    const float* kv_w     = (const float*)d_in[5];
    const float* ln_gamma = (const float*)d_in[6];
    const float* ln_beta  = (const float*)d_in[7];
    const float* ff_in_w  = (const float*)d_in[8];
    const float* ff_out_w = (const float*)d_in[9];
    const float* out_w    = (const float*)d_in[10];
    const int*   cr_idx   = (const int*)d_in[11];
    const int*   cc_idx   = (const int*)d_in[12];
    float* out = (float*)d_out;

    void *pq, *pqdet, *pqr, *pkvraw, *pk, *pv, *po, *pf, *ph;
    void *pxhi, *pxlo, *pkvwh, *plnhi, *plnlo, *pffinh, *pghi, *pglo, *pffouth;
    cudaGetSymbolAddress(&pq, g_q);
    cudaGetSymbolAddress(&pqdet, g_qdet);
    cudaGetSymbolAddress(&pqr, g_qr);
    cudaGetSymbolAddress(&pkvraw, g_kvraw);
    cudaGetSymbolAddress(&pk, g_k);
    cudaGetSymbolAddress(&pv, g_v);
    cudaGetSymbolAddress(&po, g_o);
    cudaGetSymbolAddress(&pf, g_f);
    cudaGetSymbolAddress(&ph, g_h);
    cudaGetSymbolAddress(&pxhi, g_xhi);     cudaGetSymbolAddress(&pxlo, g_xlo);
    cudaGetSymbolAddress(&pkvwh, g_kvwh);
    cudaGetSymbolAddress(&plnhi, g_lnhi);   cudaGetSymbolAddress(&plnlo, g_lnlo);
    cudaGetSymbolAddress(&pffinh, g_ffinh);
    cudaGetSymbolAddress(&pghi, g_ghi);     cudaGetSymbolAddress(&pglo, g_glo);
    cudaGetSymbolAddress(&pffouth, g_ffouth);

    int attn_smem = (2*256*SROW + 64 + 256 + 256 + 16) * 4;
    cudaFuncSetAttribute(attn_kernel, cudaFuncAttributeMaxDynamicSharedMemorySize, attn_smem);
    cudaFuncSetAttribute(gemm_nt_split, cudaFuncAttributeMaxDynamicSharedMemorySize, GEMM_SMEM);

    // ---- q preparation ----
    copy4_kernel<<<(HNUM*CDIM*HD/4 + 255)/256, 256>>>((const float4*)cls, (float4*)pq, HNUM*CDIM*HD/4);
    rms64_kernel<<<HNUM*RR, 32>>>(roots, (float*)pqr);
    scatter_kernel<<<HNUM*CRN, 64>>>(cr_idx, cr_idx + CRN, cr_w, (const float*)pqr, (float*)pq, CRN, RR);
    copy4_kernel<<<(HNUM*CDIM*HD/4 + 255)/256, 256>>>((const float4*)pq, (float4*)pqdet, HNUM*CDIM*HD/4);
    scatter_kernel<<<HNUM*SCN, 64>>>(cc_idx, cc_idx + SCN, cc_w, (const float*)pqdet, (float*)pq, SCN, CDIM);
    rms64_kernel<<<HNUM*CDIM, 32>>>((const float*)pq, (float*)pq);

    // ---- kv = x @ kv_w^T on tensor cores ----
    split_kernel<<<(BB*SS*DIN/4 + 255)/256, 256>>>((const float4*)x, (__half*)pxhi,
                                                   (__half*)pxlo, BB*SS*DIN/4);
    conv_half_kernel<<<(2*ATT*DIN/4 + 255)/256, 256>>>((const float4*)kv_w, (__half*)pkvwh,
                                                       2*ATT*DIN/4);
    gemm_nt_split<<<dim3(2*ATT/128, BB*SS/128), 256, GEMM_SMEM>>>(
        (const __half*)pxhi, (const __half*)pxlo, (const __half*)pkvwh,
        (float*)pkvraw, BB*SS, 2*ATT, DIN);
    kvsplit_kernel<<<BB*HNUM*SS, 32>>>((const float*)pkvraw, (float*)pk, (float*)pv);

    // ---- attention ----
    attn_kernel<<<dim3(BB*HNUM, CDIM/256), 256, attn_smem>>>((const float*)pq, (const float*)pk,
                                                             (const float*)pv, (float*)po);

    // ---- layernorm + split ----
    ln_split_kernel<<<BB*CDIM, 256>>>(ln_gamma, ln_beta, (const float*)po,
                                      (__half*)plnhi, (__half*)plnlo);

    // ---- FF1: f = ln @ ff_in_w^T (16384 x 6144 x 1024) ----
    conv_half_kernel<<<(2*FFN*ATT/4 + 255)/256, 256>>>((const float4*)ff_in_w, (__half*)pffinh,
                                                       2*FFN*ATT/4);
    gemm_nt_split<<<dim3(2*FFN/128, BB*CDIM/128), 256, GEMM_SMEM>>>(
        (const __half*)plnhi, (const __half*)plnlo, (const __half*)pffinh,
        (float*)pf, BB*CDIM, 2*FFN, ATT);

    // ---- gate + split ----
    {
        int n4 = BB*CDIM*FFN/4;
        gate_split_kernel<<<(n4 + 255)/256, 256>>>((const float*)pf, (__half*)pghi,
                                                   (__half*)pglo, n4);
    }

    // ---- FF2: h = gate @ ff_out_w^T (16384 x 1024 x 3072) ----
    conv_half_kernel<<<(ATT*FFN/4 + 255)/256, 256>>>((const float4*)ff_out_w, (__half*)pffouth,
                                                     ATT*FFN/4);
    gemm_nt_split<<<dim3(ATT/128, BB*CDIM/128), 256, GEMM_SMEM>>>(
        (const __half*)pghi, (const __half*)pglo, (const __half*)pffouth,
        (float*)ph, BB*CDIM, ATT, FFN);

    // ---- final ----
    final_kernel<<<BB*CDIM, 256>>>(out_w, (const float*)po, (const float*)ph, out);
}